// round 4
// baseline (speedup 1.0000x reference)
#include <cuda_runtime.h>
#include <cuda_bf16.h>
#include <cstdint>

// Problem constants (fixed by the reference)
#define NN      10000
#define KNN     32
#define DG      256
#define ODIM    256
#define XSTRIDE 512   // 2*DG

// Scratch: transformed/clipped feature table h[N][512]
__device__ float g_h[NN * XSTRIDE];

// ---- packed f32x2 helpers (dual-lane fp32 FMA, sm_100+) ----
__device__ __forceinline__ unsigned long long pack2(float v) {
    unsigned long long r;
    asm("mov.b64 %0, {%1, %1};" : "=l"(r) : "f"(v));
    return r;
}
// TIED accumulator ("+l") so ptxas keeps d in-place: FFMA2, no extra MOV.b64
__device__ __forceinline__ void ffma2(unsigned long long& d,
                                      unsigned long long a,
                                      unsigned long long b) {
    asm("fma.rn.f32x2 %0, %1, %2, %0;" : "+l"(d) : "l"(a), "l"(b));
}
__device__ __forceinline__ float2 unpack2(unsigned long long v) {
    float2 f;
    asm("mov.b64 {%0, %1}, %2;" : "=f"(f.x), "=f"(f.y) : "l"(v));
    return f;
}

__device__ __forceinline__ uint32_t smem_u32(const void* p) {
    uint32_t a;
    asm("{ .reg .u64 t; cvta.to.shared.u64 t, %1; cvt.u32.u64 %0, t; }"
        : "=r"(a) : "l"(p));
    return a;
}

// ---------------------------------------------------------------------------
// GEMM: h[i, g*256+o] = clip(fw_g[o] * sum_d x[i, g*256+d] * W_g[o,d], -1, 1)
// 128x128x8 tile, 256 threads, 8x8 micro-tile via fma.rn.f32x2 (acc packed
// along n), double-buffered SMEM, fused softmax(a).
// ---------------------------------------------------------------------------
#define BM 128
#define BN 128
#define BK 8
#define SPAD 4

__global__ __launch_bounds__(256)
void gemm_kernel(const float* __restrict__ x,
                 const float* __restrict__ W1, const float* __restrict__ a1,
                 const float* __restrict__ W2, const float* __restrict__ a2) {
    const int g  = blockIdx.z;
    const float* __restrict__ W = g ? W2 : W1;
    const float* __restrict__ a = g ? a2 : a1;
    const int i0 = blockIdx.x * BM;
    const int o0 = blockIdx.y * BN;

    __shared__ __align__(16) float As[2][BK][BM + SPAD];
    __shared__ __align__(16) float Bs[2][BK][BN + SPAD];
    __shared__ float red[256];
    __shared__ float ea[256];

    const int t  = threadIdx.x;
    const int tx = t & 15;   // n-dim (8 cols each)
    const int ty = t >> 4;   // m-dim (8 rows each)

    // ---- fused fw = softmax(a) ----
    float av_ = a[t];
    red[t] = av_; __syncthreads();
    #pragma unroll
    for (int s = 128; s > 0; s >>= 1) {
        if (t < s) red[t] = fmaxf(red[t], red[t + s]);
        __syncthreads();
    }
    float amax = red[0]; __syncthreads();
    float e = expf(av_ - amax);
    ea[t] = e; red[t] = e; __syncthreads();
    #pragma unroll
    for (int s = 128; s > 0; s >>= 1) {
        if (t < s) red[t] += red[t + s];
        __syncthreads();
    }
    float esum = red[0]; __syncthreads();
    float fwv[8];
    #pragma unroll
    for (int nn = 0; nn < 8; ++nn)
        fwv[nn] = ea[o0 + tx * 8 + nn] / esum;

    // ---- main loop ----
    const int ar = t >> 1;       // 0..127 row within tile
    const int ac = t & 1;        // 0..1 (float4 within 8-k chunk)
    const bool arow_ok = (i0 + ar) < NN;
    const float* __restrict__ xrow = x + (size_t)(i0 + ar) * XSTRIDE + g * DG + ac * 4;
    const float* __restrict__ wrow = W + (size_t)(o0 + ar) * DG + ac * 4;

    unsigned long long acc2[8][4];
    #pragma unroll
    for (int m = 0; m < 8; ++m)
        #pragma unroll
        for (int p = 0; p < 4; ++p) acc2[m][p] = 0ull;

    // prologue: stage 0
    {
        float4 avec = make_float4(0.f, 0.f, 0.f, 0.f);
        if (arow_ok) avec = *(const float4*)xrow;
        float4 bvec = *(const float4*)wrow;
        As[0][ac * 4 + 0][ar] = avec.x; As[0][ac * 4 + 1][ar] = avec.y;
        As[0][ac * 4 + 2][ar] = avec.z; As[0][ac * 4 + 3][ar] = avec.w;
        Bs[0][ac * 4 + 0][ar] = bvec.x; Bs[0][ac * 4 + 1][ar] = bvec.y;
        Bs[0][ac * 4 + 2][ar] = bvec.z; Bs[0][ac * 4 + 3][ar] = bvec.w;
    }
    __syncthreads();

    int buf = 0;
    for (int k0 = 0; k0 < DG; k0 += BK) {
        const bool has_next = (k0 + BK) < DG;
        float4 avec = make_float4(0.f, 0.f, 0.f, 0.f), bvec;
        if (has_next) {
            if (arow_ok) avec = *(const float4*)(xrow + k0 + BK);
            bvec = *(const float4*)(wrow + k0 + BK);
        }

        #pragma unroll
        for (int k = 0; k < BK; ++k) {
            float4 a0  = *(const float4*)&As[buf][k][ty * 8];
            float4 a1v = *(const float4*)&As[buf][k][ty * 8 + 4];
            ulonglong2 b01 = *(const ulonglong2*)&Bs[buf][k][tx * 8];
            ulonglong2 b23 = *(const ulonglong2*)&Bs[buf][k][tx * 8 + 4];
            unsigned long long rb[4] = {b01.x, b01.y, b23.x, b23.y};
            float ra[8] = {a0.x, a0.y, a0.z, a0.w, a1v.x, a1v.y, a1v.z, a1v.w};
            #pragma unroll
            for (int m = 0; m < 8; ++m) {
                unsigned long long am = pack2(ra[m]);
                #pragma unroll
                for (int p = 0; p < 4; ++p)
                    ffma2(acc2[m][p], am, rb[p]);
            }
        }

        if (has_next) {
            int nb = buf ^ 1;
            As[nb][ac * 4 + 0][ar] = avec.x; As[nb][ac * 4 + 1][ar] = avec.y;
            As[nb][ac * 4 + 2][ar] = avec.z; As[nb][ac * 4 + 3][ar] = avec.w;
            Bs[nb][ac * 4 + 0][ar] = bvec.x; Bs[nb][ac * 4 + 1][ar] = bvec.y;
            Bs[nb][ac * 4 + 2][ar] = bvec.z; Bs[nb][ac * 4 + 3][ar] = bvec.w;
        }
        __syncthreads();
        buf ^= 1;
    }

    // ---- epilogue: unpack, scale by fw, clip, store ----
    #pragma unroll
    for (int m = 0; m < 8; ++m) {
        int gi = i0 + ty * 8 + m;
        if (gi >= NN) continue;
        float2 c0 = unpack2(acc2[m][0]);
        float2 c1 = unpack2(acc2[m][1]);
        float2 c2 = unpack2(acc2[m][2]);
        float2 c3 = unpack2(acc2[m][3]);
        float4 v0, v1;
        v0.x = fminf(1.f, fmaxf(-1.f, c0.x * fwv[0]));
        v0.y = fminf(1.f, fmaxf(-1.f, c0.y * fwv[1]));
        v0.z = fminf(1.f, fmaxf(-1.f, c1.x * fwv[2]));
        v0.w = fminf(1.f, fmaxf(-1.f, c1.y * fwv[3]));
        v1.x = fminf(1.f, fmaxf(-1.f, c2.x * fwv[4]));
        v1.y = fminf(1.f, fmaxf(-1.f, c2.y * fwv[5]));
        v1.z = fminf(1.f, fmaxf(-1.f, c3.x * fwv[6]));
        v1.w = fminf(1.f, fmaxf(-1.f, c3.y * fwv[7]));
        float* dst = &g_h[(size_t)gi * XSTRIDE + g * DG + o0 + tx * 8];
        *(float4*)dst = v0;
        *(float4*)(dst + 4) = v1;
    }
}

// ---------------------------------------------------------------------------
// Attention v2: one block per (node, group), 256 threads.
// Neighbor rows gathered GMEM->SMEM via cp.async.bulk (bypasses L1tex),
// mbarrier transaction-count completion, compute from SMEM.
// ---------------------------------------------------------------------------
__global__ __launch_bounds__(256)
void attn_kernel(const int* __restrict__ graph, float* __restrict__ out) {
    const int i = blockIdx.x;
    const int g = blockIdx.y;

    __shared__ __align__(16) float nb[KNN][DG];   // 32KB
    __shared__ __align__(16) float ov[DG];        // 1KB
    __shared__ float score[KNN];
    __shared__ int   idxs[KNN];
    __shared__ __align__(8) unsigned long long mbar;

    const int t = threadIdx.x;
    if (t < KNN) idxs[t] = graph[(size_t)i * KNN + t];
    if (t == 0) {
        uint32_t mb = smem_u32(&mbar);
        asm volatile("mbarrier.init.shared.b64 [%0], %1;" :: "r"(mb), "r"(1) : "memory");
    }
    __syncthreads();

    if (t == 0) {
        uint32_t mb = smem_u32(&mbar);
        const uint32_t total = (KNN + 1) * DG * 4;  // 33 KB
        asm volatile("mbarrier.arrive.expect_tx.shared.b64 _, [%0], %1;"
                     :: "r"(mb), "r"(total) : "memory");
        // own row
        asm volatile("cp.async.bulk.shared::cluster.global.mbarrier::complete_tx::bytes"
                     " [%0], [%1], %2, [%3];"
                     :: "r"(smem_u32(ov)),
                        "l"(&g_h[(size_t)i * XSTRIDE + g * DG]),
                        "r"(DG * 4), "r"(mb) : "memory");
        // 32 neighbor rows (1KB each)
        #pragma unroll 4
        for (int j = 0; j < KNN; ++j) {
            asm volatile("cp.async.bulk.shared::cluster.global.mbarrier::complete_tx::bytes"
                         " [%0], [%1], %2, [%3];"
                         :: "r"(smem_u32(&nb[j][0])),
                            "l"(&g_h[(size_t)idxs[j] * XSTRIDE + g * DG]),
                            "r"(DG * 4), "r"(mb) : "memory");
        }
    }

    // wait for all 33KB (parity phase 0), acquire ordering for LDS below
    {
        uint32_t mb = smem_u32(&mbar);
        uint32_t done;
        asm volatile(
            "{\n\t.reg .pred p;\n\t"
            "mbarrier.try_wait.parity.acquire.cta.shared::cta.b64 p, [%1], 0;\n\t"
            "selp.b32 %0, 1, 0, p;\n\t}"
            : "=r"(done) : "r"(mb) : "memory");
        while (!done) {
            asm volatile(
                "{\n\t.reg .pred p;\n\t"
                "mbarrier.try_wait.parity.acquire.cta.shared::cta.b64 p, [%1], 0, 0x989680;\n\t"
                "selp.b32 %0, 1, 0, p;\n\t}"
                : "=r"(done) : "r"(mb) : "memory");
        }
    }
    __syncthreads();

    // Scores: warp w handles neighbors w, w+8, w+16, w+24
    const int lane = t & 31;
    const int w    = t >> 5;
    #pragma unroll
    for (int jj = 0; jj < 4; ++jj) {
        int j = w + jj * 8;
        float s = 0.f;
        #pragma unroll
        for (int d = lane; d < DG; d += 32) {
            float diff = ov[d] - nb[j][d];
            s = fmaf(diff, diff, s);
        }
        #pragma unroll
        for (int off = 16; off; off >>= 1) s += __shfl_xor_sync(0xffffffffu, s, off);
        if (lane == 0) score[j] = -s;
    }
    __syncthreads();

    // Softmax over 32 scores (warp 0)
    if (t < KNN) {
        float s = score[t];
        float m = s;
        #pragma unroll
        for (int off = 16; off; off >>= 1) m = fmaxf(m, __shfl_xor_sync(0xffffffffu, m, off));
        float e = __expf(s - m);
        float sum = e;
        #pragma unroll
        for (int off = 16; off; off >>= 1) sum += __shfl_xor_sync(0xffffffffu, sum, off);
        score[t] = e / sum;
    }
    __syncthreads();

    // Aggregate: out[i, g*256 + t] = sum_j att[j] * nb[j][t]
    float acc = 0.f;
    #pragma unroll
    for (int j = 0; j < KNN; ++j)
        acc = fmaf(score[j], nb[j][t], acc);
    out[(size_t)i * XSTRIDE + g * DG + t] = acc;
}

// ---------------------------------------------------------------------------
// Launch
// ---------------------------------------------------------------------------
extern "C" void kernel_launch(void* const* d_in, const int* in_sizes, int n_in,
                              void* d_out, int out_size) {
    const float* x     = (const float*)d_in[0];
    const float* W1    = (const float*)d_in[1];
    const float* a1    = (const float*)d_in[2];
    const float* W2    = (const float*)d_in[3];
    const float* a2    = (const float*)d_in[4];
    const int*   graph = (const int*)d_in[5];
    float* out = (float*)d_out;

    dim3 ggrid((NN + BM - 1) / BM, ODIM / BN, 2);
    gemm_kernel<<<ggrid, 256>>>(x, W1, a1, W2, a2);

    dim3 agrid(NN, 2);
    attn_kernel<<<agrid, 256>>>(graph, out);
}

// round 6
// speedup vs baseline: 1.5579x; 1.5579x over previous
#include <cuda_runtime.h>
#include <cuda_bf16.h>
#include <cstdint>

// Problem constants (fixed by the reference)
#define NN      10000
#define KNN     32
#define DG      256
#define ODIM    256
#define XSTRIDE 512   // 2*DG

// Scratch: transformed/clipped feature table h[N][512]
__device__ float g_h[NN * XSTRIDE];

__device__ __forceinline__ uint32_t smem_u32(const void* p) {
    uint32_t a;
    asm("{ .reg .u64 t; cvta.to.shared.u64 t, %1; cvt.u32.u64 %0, t; }"
        : "=r"(a) : "l"(p));
    return a;
}

// split a float pair into packed bf16 hi / lo pairs
__device__ __forceinline__ void cvt_pair(float f0, float f1,
                                         uint32_t& hi, uint32_t& lo) {
    __nv_bfloat162 hp = __floats2bfloat162_rn(f0, f1);
    float2 hf = __bfloat1622float2(hp);
    __nv_bfloat162 lp = __floats2bfloat162_rn(f0 - hf.x, f1 - hf.y);
    hi = *(uint32_t*)&hp;
    lo = *(uint32_t*)&lp;
}

__device__ __forceinline__ void ldm_x4(uint32_t* r, uint32_t addr) {
    asm volatile("ldmatrix.sync.aligned.m8n8.x4.shared.b16 {%0,%1,%2,%3}, [%4];"
                 : "=r"(r[0]), "=r"(r[1]), "=r"(r[2]), "=r"(r[3]) : "r"(addr));
}

__device__ __forceinline__ void mma_bf16(float* d, const uint32_t* a,
                                         const uint32_t* b) {
    asm volatile(
        "mma.sync.aligned.m16n8k16.row.col.f32.bf16.bf16.f32 "
        "{%0,%1,%2,%3}, {%4,%5,%6,%7}, {%8,%9}, {%0,%1,%2,%3};"
        : "+f"(d[0]), "+f"(d[1]), "+f"(d[2]), "+f"(d[3])
        : "r"(a[0]), "r"(a[1]), "r"(a[2]), "r"(a[3]), "r"(b[0]), "r"(b[1]));
}

// ---------------------------------------------------------------------------
// GEMM via HMMA (bf16 2-way split, 3 products, fp32 accumulate):
//   h[i, g*256+o] = clip(fw_g[o] * sum_d x[i,g*256+d] * W_g[o,d], -1, 1)
// Block: 128x128 tile, 8 warps (4m x 2n), warp tile 32x64.
// Grid (79, 2, 2) = (m-tiles, n-tiles, group).
// ---------------------------------------------------------------------------
#define STR 40   // bf16 per smem row (32 k + 8 pad): 80B stride, ldmatrix conflict-free

__global__ __launch_bounds__(256)
void gemm_mma_kernel(const float* __restrict__ x,
                     const float* __restrict__ W1, const float* __restrict__ a1,
                     const float* __restrict__ W2, const float* __restrict__ a2) {
    __shared__ __align__(16) __nv_bfloat16 sA[2][128 * STR];  // hi/lo, 10240B each
    __shared__ __align__(16) __nv_bfloat16 sB[2][128 * STR];
    __shared__ float sFW[256];
    __shared__ float red[256];

    const int t    = threadIdx.x;
    const int lane = t & 31;
    const int wid  = t >> 5;
    const int wm   = wid >> 1;       // 0..3
    const int wn   = wid & 1;        // 0..1
    const int g    = blockIdx.z;
    const int i0   = blockIdx.x * 128;
    const int o0   = blockIdx.y * 128;
    const float* __restrict__ W = g ? W2 : W1;
    const float* __restrict__ a = g ? a2 : a1;

    // ---- fused fw = softmax(a) over all 256 outputs ----
    float av = a[t];
    red[t] = av; __syncthreads();
    #pragma unroll
    for (int s = 128; s > 0; s >>= 1) {
        if (t < s) red[t] = fmaxf(red[t], red[t + s]);
        __syncthreads();
    }
    float amax = red[0]; __syncthreads();
    float e = expf(av - amax);
    red[t] = e; __syncthreads();
    #pragma unroll
    for (int s = 128; s > 0; s >>= 1) {
        if (t < s) red[t] += red[t + s];
        __syncthreads();
    }
    float esum = red[0]; __syncthreads();
    sFW[t] = e / esum;

    // ---- smem bases + per-lane ldmatrix offsets (bytes) ----
    const uint32_t sA0 = smem_u32(&sA[0][0]);
    const uint32_t sA1 = smem_u32(&sA[1][0]);
    const uint32_t sB0 = smem_u32(&sB[0][0]);
    const uint32_t sB1 = smem_u32(&sB[1][0]);
    // A: lanes 0-15 -> rows 0-15 (k low 8), lanes 16-31 -> rows 0-15 (k high 8)
    const uint32_t aoff = (uint32_t)(((wm * 32 + (lane & 15)) * STR +
                                      ((lane >> 4) & 1) * 8) * 2);
    // B (non-trans): lanes 0-7 n0-7/k0, 8-15 n0-7/k8, 16-23 n8-15/k0, 24-31 n8-15/k8
    const uint32_t boff = (uint32_t)(((wn * 64 + (lane & 7) + ((lane >> 4) & 1) * 8) * STR +
                                      ((lane >> 3) & 1) * 8) * 2);

    float acc[2][8][4];
    #pragma unroll
    for (int mt = 0; mt < 2; ++mt)
        #pragma unroll
        for (int nt = 0; nt < 8; ++nt)
            #pragma unroll
            for (int q = 0; q < 4; ++q) acc[mt][nt][q] = 0.f;

    // ---- k-chunk loop (8 chunks of 32) ----
    for (int c = 0; c < 8; ++c) {
        const int k0 = c * 32;
        // fill: each thread 4 iterations, each = one float4 of A and one of B
        #pragma unroll
        for (int q = 0; q < 4; ++q) {
            int lin = q * 256 + t;
            int row = lin >> 3;          // 0..127
            int k   = (lin & 7) * 4;     // 0..28
            // A (x rows)
            float4 v = make_float4(0.f, 0.f, 0.f, 0.f);
            if (i0 + row < NN)
                v = *(const float4*)&x[(size_t)(i0 + row) * XSTRIDE + g * DG + k0 + k];
            uint32_t h0, l0, h1, l1;
            cvt_pair(v.x, v.y, h0, l0);
            cvt_pair(v.z, v.w, h1, l1);
            *(uint2*)&sA[0][row * STR + k] = make_uint2(h0, h1);
            *(uint2*)&sA[1][row * STR + k] = make_uint2(l0, l1);
            // B (W rows = outputs)
            float4 wv = *(const float4*)&W[(size_t)(o0 + row) * DG + k0 + k];
            cvt_pair(wv.x, wv.y, h0, l0);
            cvt_pair(wv.z, wv.w, h1, l1);
            *(uint2*)&sB[0][row * STR + k] = make_uint2(h0, h1);
            *(uint2*)&sB[1][row * STR + k] = make_uint2(l0, l1);
        }
        __syncthreads();

        #pragma unroll
        for (int ks = 0; ks < 2; ++ks) {
            uint32_t ah[2][4], al[2][4];
            ldm_x4(ah[0], sA0 + aoff + ks * 32);
            ldm_x4(ah[1], sA0 + aoff + 16 * STR * 2 + ks * 32);
            ldm_x4(al[0], sA1 + aoff + ks * 32);
            ldm_x4(al[1], sA1 + aoff + 16 * STR * 2 + ks * 32);
            #pragma unroll
            for (int nt2 = 0; nt2 < 4; ++nt2) {
                uint32_t bh[4], bl[4];
                ldm_x4(bh, sB0 + boff + nt2 * 16 * STR * 2 + ks * 32);
                ldm_x4(bl, sB1 + boff + nt2 * 16 * STR * 2 + ks * 32);
                #pragma unroll
                for (int mt = 0; mt < 2; ++mt) {
                    mma_bf16(acc[mt][nt2 * 2],     ah[mt], bh);
                    mma_bf16(acc[mt][nt2 * 2],     ah[mt], bl);
                    mma_bf16(acc[mt][nt2 * 2],     al[mt], bh);
                    mma_bf16(acc[mt][nt2 * 2 + 1], ah[mt], bh + 2);
                    mma_bf16(acc[mt][nt2 * 2 + 1], ah[mt], bl + 2);
                    mma_bf16(acc[mt][nt2 * 2 + 1], al[mt], bh + 2);
                }
            }
        }
        __syncthreads();
    }

    // ---- epilogue: scale by fw, clip, store ----
    #pragma unroll
    for (int mt = 0; mt < 2; ++mt) {
        int ra = i0 + wm * 32 + mt * 16 + (lane >> 2);
        int rb = ra + 8;
        #pragma unroll
        for (int nt = 0; nt < 8; ++nt) {
            int colg = o0 + wn * 64 + nt * 8 + (lane & 3) * 2;  // 0..255
            float f0 = sFW[colg], f1 = sFW[colg + 1];
            if (ra < NN) {
                float2 v;
                v.x = fminf(1.f, fmaxf(-1.f, acc[mt][nt][0] * f0));
                v.y = fminf(1.f, fmaxf(-1.f, acc[mt][nt][1] * f1));
                *(float2*)&g_h[(size_t)ra * XSTRIDE + g * DG + colg] = v;
            }
            if (rb < NN) {
                float2 v;
                v.x = fminf(1.f, fmaxf(-1.f, acc[mt][nt][2] * f0));
                v.y = fminf(1.f, fmaxf(-1.f, acc[mt][nt][3] * f1));
                *(float2*)&g_h[(size_t)rb * XSTRIDE + g * DG + colg] = v;
            }
        }
    }
}

// ---------------------------------------------------------------------------
// Attention (round-3 proven version): one block per (node, group), 256 thr,
// neighbors in registers, MLP=8 gathers.
// ---------------------------------------------------------------------------
__global__ __launch_bounds__(256)
void attn_kernel(const int* __restrict__ graph, float* __restrict__ out) {
    const int i = blockIdx.x;
    const int g = blockIdx.y;

    __shared__ int   idxs[KNN];
    __shared__ float part[2 * KNN];
    __shared__ float score[KNN];
    __shared__ float4 agg[4][64];

    const int t = threadIdx.x;
    if (t < KNN) idxs[t] = __ldg(&graph[(size_t)i * KNN + t]);
    __syncthreads();

    const int q    = t & 63;
    const int jb   = t >> 6;
    const int w    = t >> 5;
    const int lane = t & 31;

    const float* __restrict__ base = g_h + g * DG + q * 4;
    float4 ov = __ldcg((const float4*)(base + (size_t)i * XSTRIDE));

    float4 nbv[8];
    #pragma unroll
    for (int r = 0; r < 8; ++r)
        nbv[r] = __ldcg((const float4*)(base + (size_t)idxs[4 * r + jb] * XSTRIDE));

    #pragma unroll
    for (int r = 0; r < 8; ++r) {
        float dx = ov.x - nbv[r].x, dy = ov.y - nbv[r].y;
        float dz = ov.z - nbv[r].z, dw = ov.w - nbv[r].w;
        float s = dx * dx + dy * dy + dz * dz + dw * dw;
        #pragma unroll
        for (int off = 16; off; off >>= 1) s += __shfl_xor_sync(0xffffffffu, s, off);
        if (lane == 0) part[(4 * r + jb) * 2 + (w & 1)] = s;
    }
    __syncthreads();

    if (t < KNN) {
        float s = -(part[2 * t] + part[2 * t + 1]);
        float m = s;
        #pragma unroll
        for (int off = 16; off; off >>= 1) m = fmaxf(m, __shfl_xor_sync(0xffffffffu, m, off));
        float e = __expf(s - m);
        float sum = e;
        #pragma unroll
        for (int off = 16; off; off >>= 1) sum += __shfl_xor_sync(0xffffffffu, sum, off);
        score[t] = e / sum;
    }
    __syncthreads();

    float4 acc = make_float4(0.f, 0.f, 0.f, 0.f);
    #pragma unroll
    for (int r = 0; r < 8; ++r) {
        float wt = score[4 * r + jb];
        acc.x = fmaf(wt, nbv[r].x, acc.x);
        acc.y = fmaf(wt, nbv[r].y, acc.y);
        acc.z = fmaf(wt, nbv[r].z, acc.z);
        acc.w = fmaf(wt, nbv[r].w, acc.w);
    }
    agg[jb][q] = acc;
    __syncthreads();

    if (t < 64) {
        float4 s0 = agg[0][t], s1 = agg[1][t], s2 = agg[2][t], s3 = agg[3][t];
        float4 o;
        o.x = (s0.x + s1.x) + (s2.x + s3.x);
        o.y = (s0.y + s1.y) + (s2.y + s3.y);
        o.z = (s0.z + s1.z) + (s2.z + s3.z);
        o.w = (s0.w + s1.w) + (s2.w + s3.w);
        *(float4*)&out[(size_t)i * XSTRIDE + g * DG + t * 4] = o;
    }
}

// ---------------------------------------------------------------------------
// Launch
// ---------------------------------------------------------------------------
extern "C" void kernel_launch(void* const* d_in, const int* in_sizes, int n_in,
                              void* d_out, int out_size) {
    const float* x     = (const float*)d_in[0];
    const float* W1    = (const float*)d_in[1];
    const float* a1    = (const float*)d_in[2];
    const float* W2    = (const float*)d_in[3];
    const float* a2    = (const float*)d_in[4];
    const int*   graph = (const int*)d_in[5];
    float* out = (float*)d_out;

    dim3 ggrid((NN + 127) / 128, 2, 2);
    gemm_mma_kernel<<<ggrid, 256>>>(x, W1, a1, W2, a2);

    dim3 agrid(NN, 2);
    attn_kernel<<<agrid, 256>>>(graph, out);
}